// round 16
// baseline (speedup 1.0000x reference)
#include <cuda_runtime.h>
#include <cuda_fp16.h>
#include <math.h>

#define NE 8
#define TOPK 2
#define DM 1024
#define DH 4096
#define T_TOK 4096
#define NPAIR (T_TOK*TOPK)
#define KS 32          // k-tile in elements (halfs)
#define HLD 40         // smem row stride in halfs (padded)
#define TILE_H (128*HLD)   // halfs per tile buffer
#define NSTG 4

// ---------------- scratch (device globals; no allocation) ----------------
__device__ int    g_count[NE];
__device__ int    g_off[NE];
__device__ int    g_cursor[NE];
__device__ int    g_pair_tok[NPAIR];
__device__ float  g_pair_w[NPAIR];
__device__ int    g_tok_e[T_TOK*TOPK];
__device__ float  g_tok_w[T_TOK*TOPK];
__device__ __half g_acth[(size_t)NPAIR*DH];    // 64 MB fp16 activations
__device__ __half g_w0h[(size_t)NE*DM*DH];     // [e][n=DH][k=DM] fp16 transposed
__device__ __half g_w1h[(size_t)NE*DM*DH];
__device__ __half g_w2h[(size_t)NE*DH*DM];     // [e][n=DM][k=DH]
__device__ __half g_xh[(size_t)T_TOK*DM];      // fp16 activations

__device__ __forceinline__ void mma_f16(float c[4], unsigned a0, unsigned a1,
                                        unsigned a2, unsigned a3,
                                        unsigned b0, unsigned b1) {
    asm volatile(
        "mma.sync.aligned.m16n8k16.row.col.f32.f16.f16.f32 "
        "{%0,%1,%2,%3}, {%4,%5,%6,%7}, {%8,%9}, {%0,%1,%2,%3};\n"
        : "+f"(c[0]), "+f"(c[1]), "+f"(c[2]), "+f"(c[3])
        : "r"(a0), "r"(a1), "r"(a2), "r"(a3), "r"(b0), "r"(b1));
}

__device__ __forceinline__ void ldsm4(unsigned r[4], unsigned addr) {
    asm volatile("ldmatrix.sync.aligned.m8n8.x4.shared.b16 {%0,%1,%2,%3}, [%4];"
                 : "=r"(r[0]), "=r"(r[1]), "=r"(r[2]), "=r"(r[3]) : "r"(addr));
}

__device__ __forceinline__ void red_add_f32x2(float* addr, float v0, float v1) {
    asm volatile("red.global.add.v2.f32 [%0], {%1, %2};"
                 :: "l"(addr), "f"(v0), "f"(v1) : "memory");
}

__device__ __forceinline__ unsigned sptr(const void* p) {
    return (unsigned)__cvta_generic_to_shared(p);
}
__device__ __forceinline__ void cp16(unsigned dst, const void* src, int srcbytes) {
    asm volatile("cp.async.cg.shared.global [%0], [%1], 16, %2;\n"
                 :: "r"(dst), "l"(src), "r"(srcbytes));
}
__device__ __forceinline__ void cp_commit() { asm volatile("cp.async.commit_group;\n"); }
__device__ __forceinline__ void cp_wait2()  { asm volatile("cp.async.wait_group 2;\n"); }

// ---------------- weight prep: W0/W1 for 4 experts, [k=DM][n=DH] -> [n][k] fp16 ----------------
// grid.z in [0,8): expert = ebase + z/2, tensor = z%2
__global__ void k_tw01(const float* __restrict__ W0, const float* __restrict__ W1,
                       int ebase) {
    __shared__ float t[64][65];
    int e = ebase + (blockIdx.z >> 1);
    const float* I;
    __half* O;
    if ((blockIdx.z & 1) == 0) {
        I = W0 + (size_t)e*DM*DH;  O = g_w0h + (size_t)e*DM*DH;
    } else {
        I = W1 + (size_t)e*DM*DH;  O = g_w1h + (size_t)e*DM*DH;
    }
    int n0 = blockIdx.x*64, k0 = blockIdx.y*64;
    int tx = threadIdx.x, ty = threadIdx.y;   // (32, 8)
#pragma unroll
    for (int i = ty; i < 64; i += 8) {
        t[i][tx]      = I[(size_t)(k0+i)*DH + n0 + tx];
        t[i][tx + 32] = I[(size_t)(k0+i)*DH + n0 + tx + 32];
    }
    __syncthreads();
#pragma unroll
    for (int j = ty; j < 64; j += 8) {
        __half2 v = __floats2half2_rn(t[2*tx][j], t[2*tx+1][j]);
        *(__half2*)&O[(size_t)(n0+j)*DM + k0 + 2*tx] = v;
    }
}

// ---------------- weight prep: W2 all experts, [k=DH][n=DM] -> [n][k] fp16 ----------------
__global__ void k_tw2(const float* __restrict__ W2) {
    __shared__ float t[64][65];
    int e = blockIdx.z;
    const float* I = W2 + (size_t)e*DH*DM;
    __half* O = g_w2h + (size_t)e*DH*DM;
    int n0 = blockIdx.x*64, k0 = blockIdx.y*64;
    int tx = threadIdx.x, ty = threadIdx.y;
#pragma unroll
    for (int i = ty; i < 64; i += 8) {
        t[i][tx]      = I[(size_t)(k0+i)*DM + n0 + tx];
        t[i][tx + 32] = I[(size_t)(k0+i)*DM + n0 + tx + 32];
    }
    __syncthreads();
#pragma unroll
    for (int j = ty; j < 64; j += 8) {
        __half2 v = __floats2half2_rn(t[2*tx][j], t[2*tx+1][j]);
        *(__half2*)&O[(size_t)(n0+j)*DH + k0 + 2*tx] = v;
    }
}

// ---------------- routing + x->fp16 fused ----------------
__global__ void k_route(const float* __restrict__ x,
                        const float* __restrict__ Wg,
                        const float* __restrict__ bg) {
    int t = blockIdx.x;
    int tid = threadIdx.x;
    const float* xr = x + (size_t)t*DM;
    __half* xh = g_xh + (size_t)t*DM;
    float acc[NE];
#pragma unroll
    for (int e = 0; e < NE; e++) acc[e] = 0.f;
    for (int i = tid; i < DM; i += 256) {
        float xv = xr[i];
        xh[i] = __float2half(xv);
#pragma unroll
        for (int e = 0; e < NE; e++) acc[e] += xv * Wg[i*NE + e];
    }
    __shared__ float s[NE][256];
#pragma unroll
    for (int e = 0; e < NE; e++) s[e][tid] = acc[e];
    __syncthreads();
    for (int off = 128; off > 0; off >>= 1) {
        if (tid < off) {
#pragma unroll
            for (int e = 0; e < NE; e++) s[e][tid] += s[e][tid + off];
        }
        __syncthreads();
    }
    if (tid == 0) {
        float v[NE];
#pragma unroll
        for (int e = 0; e < NE; e++) v[e] = s[e][0] + bg[e];
        int i0 = 0;
#pragma unroll
        for (int e = 1; e < NE; e++) if (v[e] > v[i0]) i0 = e;
        int i1 = (i0 == 0) ? 1 : 0;
#pragma unroll
        for (int e = 0; e < NE; e++) if (e != i0 && v[e] > v[i1]) i1 = e;
        float e1 = expf(v[i1] - v[i0]);
        float inv = 1.f / (1.f + e1);
        g_tok_e[2*t]   = i0;  g_tok_w[2*t]   = inv;
        g_tok_e[2*t+1] = i1;  g_tok_w[2*t+1] = e1 * inv;
        atomicAdd(&g_count[i0], 1);
        atomicAdd(&g_count[i1], 1);
    }
}

// ---------------- scan (thread 0) + compact, single block ----------------
__global__ void k_assign() {
    if (threadIdx.x == 0) {
        int o = 0;
        for (int e = 0; e < NE; e++) {
            g_off[e] = o;
            g_cursor[e] = o;
            o += g_count[e];
        }
    }
    __syncthreads();
    for (int t = threadIdx.x; t < T_TOK; t += 1024) {
#pragma unroll
        for (int k = 0; k < TOPK; k++) {
            int e = g_tok_e[2*t + k];
            int pos = atomicAdd(&g_cursor[e], 1);
            g_pair_tok[pos] = t;
            g_pair_w[pos]   = g_tok_w[2*t + k];
        }
    }
}

// ================= pass A: act = (x@W0+b0)*silu(x@W1+b1), experts [ebase, ebase+gridDim.z) =================
__global__ void __launch_bounds__(512,1) k_mlp1(const float* __restrict__ b0,
                                                const float* __restrict__ b1,
                                                int ebase) {
    int e   = ebase + blockIdx.z;
    int cnt = g_count[e];
    int m0  = blockIdx.y * 128;
    if (m0 >= cnt) return;
    int off = g_off[e];
    int n0  = blockIdx.x * 128;

    const __half* B0g = g_w0h + (size_t)e*DM*DH;   // [n][k]
    const __half* B1g = g_w1h + (size_t)e*DM*DH;

    extern __shared__ __half sh[];
    __half* As  = sh;                     // [4][128][40]
    __half* Bs0 = As + NSTG*TILE_H;
    __half* Bs1 = Bs0 + NSTG*TILE_H;
    int*  toks = (int*)(Bs1 + NSTG*TILE_H);

    int tid = threadIdx.x;
    if (tid < 128) {
        int m = m0 + tid;
        toks[tid] = (m < cnt) ? g_pair_tok[off + m] : -1;
    }
    __syncthreads();

    int lrow = tid >> 2;
    int lch  = (tid & 3) * 8;
    int tok  = toks[lrow];
    const __half* asrc = g_xh + (size_t)(tok < 0 ? 0 : tok)*DM + lch;
    int asz = (tok < 0) ? 0 : 16;
    unsigned adst = sptr(As + lrow*HLD + lch);
    const __half* b0src = B0g + (size_t)(n0 + lrow)*DM + lch;
    const __half* b1src = B1g + (size_t)(n0 + lrow)*DM + lch;
    unsigned b0dst = sptr(Bs0 + lrow*HLD + lch);
    unsigned b1dst = sptr(Bs1 + lrow*HLD + lch);

    int lane = tid & 31, warp = tid >> 5;
    int wm = warp & 3, wn = warp >> 2;
    int g  = lane >> 2, tig = lane & 3;

    unsigned smb = sptr(As);
    unsigned aLA  = smb + ((wm*32 + (lane & 15))*HLD + (lane >> 4)*8)*2;
    unsigned bRow = wn*32 + (lane & 7) + (lane >> 4)*8;
    unsigned bCol = ((lane >> 3) & 1)*8;
    unsigned b0LA = smb + NSTG*TILE_H*2 + (bRow*HLD + bCol)*2;
    unsigned b1LA = b0LA + NSTG*TILE_H*2;

    float ch[2][4][4], cg[2][4][4];
#pragma unroll
    for (int mi = 0; mi < 2; mi++)
#pragma unroll
        for (int ni = 0; ni < 4; ni++)
#pragma unroll
            for (int j = 0; j < 4; j++) { ch[mi][ni][j] = 0.f; cg[mi][ni][j] = 0.f; }

#define LOAD1(stage, kk0)  {                              \
        unsigned so = (stage)*TILE_H*2;                   \
        cp16(adst  + so, asrc  + (kk0), asz);             \
        cp16(b0dst + so, b0src + (kk0), 16);              \
        cp16(b1dst + so, b1src + (kk0), 16);              \
        cp_commit(); }

    LOAD1(0, 0);
    LOAD1(1, KS);
    LOAD1(2, 2*KS);

    const int NK = DM / KS;
    for (int kt = 0; kt < NK; kt++) {
        int cur = kt % NSTG;
        cp_wait2();
        __syncthreads();
        if (kt + 3 < NK) { LOAD1((kt + 3) % NSTG, (kt + 3)*KS); }
        else             { cp_commit(); }   // empty group drain

        unsigned so = cur*(unsigned)(TILE_H*2);
#pragma unroll
        for (int ks = 0; ks < KS; ks += 16) {
            unsigned A0[4], A1[4], P0[4], P1[4], Q0[4], Q1[4];
            ldsm4(A0, aLA  + so + ks*2);
            ldsm4(A1, aLA  + so + ks*2 + 16*HLD*2);
            ldsm4(P0, b0LA + so + ks*2);
            ldsm4(P1, b0LA + so + ks*2 + 16*HLD*2);
            ldsm4(Q0, b1LA + so + ks*2);
            ldsm4(Q1, b1LA + so + ks*2 + 16*HLD*2);
            mma_f16(ch[0][0], A0[0],A0[1],A0[2],A0[3], P0[0],P0[1]);
            mma_f16(ch[1][0], A1[0],A1[1],A1[2],A1[3], P0[0],P0[1]);
            mma_f16(ch[0][1], A0[0],A0[1],A0[2],A0[3], P0[2],P0[3]);
            mma_f16(ch[1][1], A1[0],A1[1],A1[2],A1[3], P0[2],P0[3]);
            mma_f16(ch[0][2], A0[0],A0[1],A0[2],A0[3], P1[0],P1[1]);
            mma_f16(ch[1][2], A1[0],A1[1],A1[2],A1[3], P1[0],P1[1]);
            mma_f16(ch[0][3], A0[0],A0[1],A0[2],A0[3], P1[2],P1[3]);
            mma_f16(ch[1][3], A1[0],A1[1],A1[2],A1[3], P1[2],P1[3]);
            mma_f16(cg[0][0], A0[0],A0[1],A0[2],A0[3], Q0[0],Q0[1]);
            mma_f16(cg[1][0], A1[0],A1[1],A1[2],A1[3], Q0[0],Q0[1]);
            mma_f16(cg[0][1], A0[0],A0[1],A0[2],A0[3], Q0[2],Q0[3]);
            mma_f16(cg[1][1], A1[0],A1[1],A1[2],A1[3], Q0[2],Q0[3]);
            mma_f16(cg[0][2], A0[0],A0[1],A0[2],A0[3], Q1[0],Q1[1]);
            mma_f16(cg[1][2], A1[0],A1[1],A1[2],A1[3], Q1[0],Q1[1]);
            mma_f16(cg[0][3], A0[0],A0[1],A0[2],A0[3], Q1[2],Q1[3]);
            mma_f16(cg[1][3], A1[0],A1[1],A1[2],A1[3], Q1[2],Q1[3]);
        }
    }

    const float* b0p = b0 + (size_t)e*DH;
    const float* b1p = b1 + (size_t)e*DH;
#pragma unroll
    for (int mi = 0; mi < 2; mi++) {
#pragma unroll
        for (int hh = 0; hh < 2; hh++) {
            int r = m0 + wm*32 + mi*16 + g + hh*8;
            if (r < cnt) {
                size_t row = (size_t)(off + r);
#pragma unroll
                for (int ni = 0; ni < 4; ni++) {
                    int c = n0 + wn*32 + ni*8 + tig*2;
                    float h0 = ch[mi][ni][hh*2+0] + b0p[c];
                    float g0 = cg[mi][ni][hh*2+0] + b1p[c];
                    float h1 = ch[mi][ni][hh*2+1] + b0p[c+1];
                    float g1 = cg[mi][ni][hh*2+1] + b1p[c+1];
                    float o0 = h0 * (g0 / (1.f + expf(-g0)));
                    float o1 = h1 * (g1 / (1.f + expf(-g1)));
                    *(__half2*)&g_acth[row*DH + c] = __floats2half2_rn(o0, o1);
                }
            }
        }
    }
}

// ================= pass B: out[token] += w * (act @ W2 + b2), all experts =================
__global__ void __launch_bounds__(512,1) k_mlp2(const float* __restrict__ b2,
                                                float* __restrict__ out) {
    int e   = blockIdx.z;
    int cnt = g_count[e];
    int m0  = blockIdx.y * 128;
    if (m0 >= cnt) return;
    int off = g_off[e];
    int n0  = blockIdx.x * 128;

    const __half* Bg = g_w2h + (size_t)e*DH*DM;   // [n][k]

    extern __shared__ __half sh[];
    __half* As = sh;                   // [4][128][40]
    __half* Bs = As + NSTG*TILE_H;

    int tid = threadIdx.x;
    int lrow = tid >> 2;
    int lch  = (tid & 3) * 8;
    int m = m0 + lrow;
    int ok = (m < cnt);
    const __half* asrc = g_acth + (size_t)(ok ? (off + m) : 0)*DH + lch;
    int asz = ok ? 16 : 0;
    unsigned adst = sptr(As + lrow*HLD + lch);
    const __half* bsrc = Bg + (size_t)(n0 + lrow)*DH + lch;
    unsigned bdst = sptr(Bs + lrow*HLD + lch);

    int lane = tid & 31, warp = tid >> 5;
    int wm = warp & 3, wn = warp >> 2;
    int g  = lane >> 2, tig = lane & 3;

    unsigned smb = sptr(As);
    unsigned aLA  = smb + ((wm*32 + (lane & 15))*HLD + (lane >> 4)*8)*2;
    unsigned bRow = wn*32 + (lane & 7) + (lane >> 4)*8;
    unsigned bCol = ((lane >> 3) & 1)*8;
    unsigned bLA  = smb + NSTG*TILE_H*2 + (bRow*HLD + bCol)*2;

    float acc[2][4][4];
#pragma unroll
    for (int mi = 0; mi < 2; mi++)
#pragma unroll
        for (int ni = 0; ni < 4; ni++)
#pragma unroll
            for (int j = 0; j < 4; j++) acc[mi][ni][j] = 0.f;

#define LOAD2(stage, kk0)  {                              \
        unsigned so = (stage)*TILE_H*2;                   \
        cp16(adst + so, asrc + (kk0), asz);               \
        cp16(bdst + so, bsrc + (kk0), 16);                \
        cp_commit(); }

    LOAD2(0, 0);
    LOAD2(1, KS);
    LOAD2(2, 2*KS);

    const int NK = DH / KS;
    for (int kt = 0; kt < NK; kt++) {
        int cur = kt % NSTG;
        cp_wait2();
        __syncthreads();
        if (kt + 3 < NK) { LOAD2((kt + 3) % NSTG, (kt + 3)*KS); }
        else             { cp_commit(); }   // empty group drain

        unsigned so = cur*(unsigned)(TILE_H*2);
#pragma unroll
        for (int ks = 0; ks < KS; ks += 16) {
            unsigned A0[4], A1[4], P0[4], P1[4];
            ldsm4(A0, aLA + so + ks*2);
            ldsm4(A1, aLA + so + ks*2 + 16*HLD*2);
            ldsm4(P0, bLA + so + ks*2);
            ldsm4(P1, bLA + so + ks*2 + 16*HLD*2);
            mma_f16(acc[0][0], A0[0],A0[1],A0[2],A0[3], P0[0],P0[1]);
            mma_f16(acc[1][0], A1[0],A1[1],A1[2],A1[3], P0[0],P0[1]);
            mma_f16(acc[0][1], A0[0],A0[1],A0[2],A0[3], P0[2],P0[3]);
            mma_f16(acc[1][1], A1[0],A1[1],A1[2],A1[3], P0[2],P0[3]);
            mma_f16(acc[0][2], A0[0],A0[1],A0[2],A0[3], P1[0],P1[1]);
            mma_f16(acc[1][2], A1[0],A1[1],A1[2],A1[3], P1[0],P1[1]);
            mma_f16(acc[0][3], A0[0],A0[1],A0[2],A0[3], P1[2],P1[3]);
            mma_f16(acc[1][3], A1[0],A1[1],A1[2],A1[3], P1[2],P1[3]);
        }
    }

    const float* b2p = b2 + (size_t)e*DM;
#pragma unroll
    for (int mi = 0; mi < 2; mi++) {
#pragma unroll
        for (int hh = 0; hh < 2; hh++) {
            int r = m0 + wm*32 + mi*16 + g + hh*8;
            if (r < cnt) {
                int tokp = g_pair_tok[off + r];
                float w = g_pair_w[off + r];
                float* orow = out + (size_t)tokp*DM;
#pragma unroll
                for (int ni = 0; ni < 4; ni++) {
                    int c = n0 + wn*32 + ni*8 + tig*2;
                    red_add_f32x2(&orow[c],
                                  w * (acc[mi][ni][hh*2+0] + b2p[c]),
                                  w * (acc[mi][ni][hh*2+1] + b2p[c+1]));
                }
            }
        }
    }
}

// ---------------- launch ----------------
#define SMEM1 (3*NSTG*TILE_H*2 + 128*4)
#define SMEM2 (2*NSTG*TILE_H*2)

extern "C" void kernel_launch(void* const* d_in, const int* in_sizes, int n_in,
                              void* d_out, int out_size) {
    const float* x  = (const float*)d_in[0];
    const float* Wg = (const float*)d_in[1];
    const float* bg = (const float*)d_in[2];
    const float* W0 = (const float*)d_in[3];
    const float* b0 = (const float*)d_in[4];
    const float* W1 = (const float*)d_in[5];
    const float* b1 = (const float*)d_in[6];
    const float* W2 = (const float*)d_in[7];
    const float* b2 = (const float*)d_in[8];
    float* out = (float*)d_out;

    static cudaStream_t s2 = 0;
    static cudaEvent_t eFork = 0, eA = 0, eB = 0, eC = 0;
    if (!s2) {
        cudaFuncSetAttribute(k_mlp1, cudaFuncAttributeMaxDynamicSharedMemorySize, SMEM1);
        cudaFuncSetAttribute(k_mlp2, cudaFuncAttributeMaxDynamicSharedMemorySize, SMEM2);
        cudaStreamCreateWithFlags(&s2, cudaStreamNonBlocking);
        cudaEventCreateWithFlags(&eFork, cudaEventDisableTiming);
        cudaEventCreateWithFlags(&eA, cudaEventDisableTiming);
        cudaEventCreateWithFlags(&eB, cudaEventDisableTiming);
        cudaEventCreateWithFlags(&eC, cudaEventDisableTiming);
    }

    int* cntd; cudaGetSymbolAddress((void**)&cntd, g_count);

    // fork: weight conversions on s2 (halved W0/W1, then all W2)
    cudaEventRecord(eFork, 0);
    cudaStreamWaitEvent(s2, eFork, 0);
    k_tw01<<<dim3(DH/64, DM/64, 8), dim3(32,8), 0, s2>>>(W0, W1, 0);
    cudaEventRecord(eA, s2);
    k_tw01<<<dim3(DH/64, DM/64, 8), dim3(32,8), 0, s2>>>(W0, W1, 4);
    cudaEventRecord(eB, s2);
    k_tw2<<<dim3(DM/64, DH/64, NE), dim3(32,8), 0, s2>>>(W2);
    cudaEventRecord(eC, s2);

    // main stream: reset + routing chain
    cudaMemsetAsync(out, 0, (size_t)T_TOK*DM*sizeof(float), 0);
    cudaMemsetAsync(cntd, 0, NE*sizeof(int), 0);
    k_route <<<T_TOK, 256>>>(x, Wg, bg);
    k_assign<<<1, 1024>>>();

    // mlp1 in two halves, each gated only by its tw01 half
    cudaStreamWaitEvent(0, eA, 0);
    k_mlp1<<<dim3(DH/128, 32, 4), 512, SMEM1>>>(b0, b1, 0);
    cudaStreamWaitEvent(0, eB, 0);
    k_mlp1<<<dim3(DH/128, 32, 4), 512, SMEM1>>>(b0, b1, 4);

    cudaStreamWaitEvent(0, eC, 0);
    k_mlp2<<<dim3(DM/128, 32, NE), 512, SMEM2>>>(b2, out);
}

// round 17
// speedup vs baseline: 1.0131x; 1.0131x over previous
#include <cuda_runtime.h>
#include <cuda_fp16.h>
#include <math.h>

#define NE 8
#define TOPK 2
#define DM 1024
#define DH 4096
#define T_TOK 4096
#define NPAIR (T_TOK*TOPK)
#define KS 32          // k-tile in elements (halfs)
#define HLD 40         // smem row stride in halfs (padded)
#define TILE_H (128*HLD)   // halfs per tile buffer
#define NSTG 4

// ---------------- scratch (device globals; no allocation) ----------------
__device__ int    g_count[NE];
__device__ int    g_off[NE];
__device__ int    g_cursor[NE];
__device__ int    g_pair_tok[NPAIR];
__device__ float  g_pair_w[NPAIR];
__device__ int    g_tok_e[T_TOK*TOPK];
__device__ float  g_tok_w[T_TOK*TOPK];
__device__ __half g_acth[(size_t)NPAIR*DH];    // 64 MB fp16 activations
__device__ __half g_w0h[(size_t)NE*DM*DH];     // [e][n=DH][k=DM] fp16 transposed
__device__ __half g_w1h[(size_t)NE*DM*DH];
__device__ __half g_w2h[(size_t)NE*DH*DM];     // [e][n=DM][k=DH]
__device__ __half g_xh[(size_t)T_TOK*DM];      // fp16 activations

__device__ __forceinline__ void mma_f16(float c[4], unsigned a0, unsigned a1,
                                        unsigned a2, unsigned a3,
                                        unsigned b0, unsigned b1) {
    asm volatile(
        "mma.sync.aligned.m16n8k16.row.col.f32.f16.f16.f32 "
        "{%0,%1,%2,%3}, {%4,%5,%6,%7}, {%8,%9}, {%0,%1,%2,%3};\n"
        : "+f"(c[0]), "+f"(c[1]), "+f"(c[2]), "+f"(c[3])
        : "r"(a0), "r"(a1), "r"(a2), "r"(a3), "r"(b0), "r"(b1));
}

__device__ __forceinline__ void ldsm4(unsigned r[4], unsigned addr) {
    asm volatile("ldmatrix.sync.aligned.m8n8.x4.shared.b16 {%0,%1,%2,%3}, [%4];"
                 : "=r"(r[0]), "=r"(r[1]), "=r"(r[2]), "=r"(r[3]) : "r"(addr));
}

__device__ __forceinline__ void red_add_f32x2(float* addr, float v0, float v1) {
    asm volatile("red.global.add.v2.f32 [%0], {%1, %2};"
                 :: "l"(addr), "f"(v0), "f"(v1) : "memory");
}

__device__ __forceinline__ unsigned sptr(const void* p) {
    return (unsigned)__cvta_generic_to_shared(p);
}
__device__ __forceinline__ void cp16(unsigned dst, const void* src, int srcbytes) {
    asm volatile("cp.async.cg.shared.global [%0], [%1], 16, %2;\n"
                 :: "r"(dst), "l"(src), "r"(srcbytes));
}
__device__ __forceinline__ void cp_commit() { asm volatile("cp.async.commit_group;\n"); }
__device__ __forceinline__ void cp_wait2()  { asm volatile("cp.async.wait_group 2;\n"); }

// ---------------- weight prep: W0/W1 for 4 experts, [k=DM][n=DH] -> [n][k] fp16 ----------------
// grid.z in [0,8): expert = ebase + z/2, tensor = z%2
__global__ void k_tw01(const float* __restrict__ W0, const float* __restrict__ W1,
                       int ebase) {
    __shared__ float t[64][65];
    int e = ebase + (blockIdx.z >> 1);
    const float* I;
    __half* O;
    if ((blockIdx.z & 1) == 0) {
        I = W0 + (size_t)e*DM*DH;  O = g_w0h + (size_t)e*DM*DH;
    } else {
        I = W1 + (size_t)e*DM*DH;  O = g_w1h + (size_t)e*DM*DH;
    }
    int n0 = blockIdx.x*64, k0 = blockIdx.y*64;
    int tx = threadIdx.x, ty = threadIdx.y;   // (32, 8)
#pragma unroll
    for (int i = ty; i < 64; i += 8) {
        t[i][tx]      = I[(size_t)(k0+i)*DH + n0 + tx];
        t[i][tx + 32] = I[(size_t)(k0+i)*DH + n0 + tx + 32];
    }
    __syncthreads();
#pragma unroll
    for (int j = ty; j < 64; j += 8) {
        __half2 v = __floats2half2_rn(t[2*tx][j], t[2*tx+1][j]);
        *(__half2*)&O[(size_t)(n0+j)*DM + k0 + 2*tx] = v;
    }
}

// ---------------- weight prep: W2 all experts, [k=DH][n=DM] -> [n][k] fp16 ----------------
__global__ void k_tw2(const float* __restrict__ W2) {
    __shared__ float t[64][65];
    int e = blockIdx.z;
    const float* I = W2 + (size_t)e*DH*DM;
    __half* O = g_w2h + (size_t)e*DH*DM;
    int n0 = blockIdx.x*64, k0 = blockIdx.y*64;
    int tx = threadIdx.x, ty = threadIdx.y;
#pragma unroll
    for (int i = ty; i < 64; i += 8) {
        t[i][tx]      = I[(size_t)(k0+i)*DM + n0 + tx];
        t[i][tx + 32] = I[(size_t)(k0+i)*DM + n0 + tx + 32];
    }
    __syncthreads();
#pragma unroll
    for (int j = ty; j < 64; j += 8) {
        __half2 v = __floats2half2_rn(t[2*tx][j], t[2*tx+1][j]);
        *(__half2*)&O[(size_t)(n0+j)*DH + k0 + 2*tx] = v;
    }
}

// ---------------- routing + x->fp16 fused ----------------
__global__ void k_route(const float* __restrict__ x,
                        const float* __restrict__ Wg,
                        const float* __restrict__ bg) {
    int t = blockIdx.x;
    int tid = threadIdx.x;
    const float* xr = x + (size_t)t*DM;
    __half* xh = g_xh + (size_t)t*DM;
    float acc[NE];
#pragma unroll
    for (int e = 0; e < NE; e++) acc[e] = 0.f;
    for (int i = tid; i < DM; i += 256) {
        float xv = xr[i];
        xh[i] = __float2half(xv);
#pragma unroll
        for (int e = 0; e < NE; e++) acc[e] += xv * Wg[i*NE + e];
    }
    __shared__ float s[NE][256];
#pragma unroll
    for (int e = 0; e < NE; e++) s[e][tid] = acc[e];
    __syncthreads();
    for (int off = 128; off > 0; off >>= 1) {
        if (tid < off) {
#pragma unroll
            for (int e = 0; e < NE; e++) s[e][tid] += s[e][tid + off];
        }
        __syncthreads();
    }
    if (tid == 0) {
        float v[NE];
#pragma unroll
        for (int e = 0; e < NE; e++) v[e] = s[e][0] + bg[e];
        int i0 = 0;
#pragma unroll
        for (int e = 1; e < NE; e++) if (v[e] > v[i0]) i0 = e;
        int i1 = (i0 == 0) ? 1 : 0;
#pragma unroll
        for (int e = 0; e < NE; e++) if (e != i0 && v[e] > v[i1]) i1 = e;
        float e1 = expf(v[i1] - v[i0]);
        float inv = 1.f / (1.f + e1);
        g_tok_e[2*t]   = i0;  g_tok_w[2*t]   = inv;
        g_tok_e[2*t+1] = i1;  g_tok_w[2*t+1] = e1 * inv;
        atomicAdd(&g_count[i0], 1);
        atomicAdd(&g_count[i1], 1);
    }
}

// ---------------- scan (thread 0) + compact, single block ----------------
__global__ void k_assign() {
    if (threadIdx.x == 0) {
        int o = 0;
        for (int e = 0; e < NE; e++) {
            g_off[e] = o;
            g_cursor[e] = o;
            o += g_count[e];
        }
    }
    __syncthreads();
    for (int t = threadIdx.x; t < T_TOK; t += 1024) {
#pragma unroll
        for (int k = 0; k < TOPK; k++) {
            int e = g_tok_e[2*t + k];
            int pos = atomicAdd(&g_cursor[e], 1);
            g_pair_tok[pos] = t;
            g_pair_w[pos]   = g_tok_w[2*t + k];
        }
    }
}

// ================= pass A: act = (x@W0+b0)*silu(x@W1+b1), experts [ebase, ebase+gridDim.z) =================
__global__ void __launch_bounds__(512,1) k_mlp1(const float* __restrict__ b0,
                                                const float* __restrict__ b1,
                                                int ebase) {
    int e   = ebase + blockIdx.z;
    int cnt = g_count[e];
    int m0  = blockIdx.y * 128;
    if (m0 >= cnt) return;
    int off = g_off[e];
    int n0  = blockIdx.x * 128;

    const __half* B0g = g_w0h + (size_t)e*DM*DH;   // [n][k]
    const __half* B1g = g_w1h + (size_t)e*DM*DH;

    extern __shared__ __half sh[];
    __half* As  = sh;                     // [4][128][40]
    __half* Bs0 = As + NSTG*TILE_H;
    __half* Bs1 = Bs0 + NSTG*TILE_H;
    int*  toks = (int*)(Bs1 + NSTG*TILE_H);

    int tid = threadIdx.x;
    if (tid < 128) {
        int m = m0 + tid;
        toks[tid] = (m < cnt) ? g_pair_tok[off + m] : -1;
    }
    __syncthreads();

    int lrow = tid >> 2;
    int lch  = (tid & 3) * 8;
    int tok  = toks[lrow];
    const __half* asrc = g_xh + (size_t)(tok < 0 ? 0 : tok)*DM + lch;
    int asz = (tok < 0) ? 0 : 16;
    unsigned adst = sptr(As + lrow*HLD + lch);
    const __half* b0src = B0g + (size_t)(n0 + lrow)*DM + lch;
    const __half* b1src = B1g + (size_t)(n0 + lrow)*DM + lch;
    unsigned b0dst = sptr(Bs0 + lrow*HLD + lch);
    unsigned b1dst = sptr(Bs1 + lrow*HLD + lch);

    int lane = tid & 31, warp = tid >> 5;
    int wm = warp & 3, wn = warp >> 2;
    int g  = lane >> 2, tig = lane & 3;

    unsigned smb = sptr(As);
    unsigned aLA  = smb + ((wm*32 + (lane & 15))*HLD + (lane >> 4)*8)*2;
    unsigned bRow = wn*32 + (lane & 7) + (lane >> 4)*8;
    unsigned bCol = ((lane >> 3) & 1)*8;
    unsigned b0LA = smb + NSTG*TILE_H*2 + (bRow*HLD + bCol)*2;
    unsigned b1LA = b0LA + NSTG*TILE_H*2;

    float ch[2][4][4], cg[2][4][4];
#pragma unroll
    for (int mi = 0; mi < 2; mi++)
#pragma unroll
        for (int ni = 0; ni < 4; ni++)
#pragma unroll
            for (int j = 0; j < 4; j++) { ch[mi][ni][j] = 0.f; cg[mi][ni][j] = 0.f; }

#define LOAD1(stage, kk0)  {                              \
        unsigned so = (stage)*TILE_H*2;                   \
        cp16(adst  + so, asrc  + (kk0), asz);             \
        cp16(b0dst + so, b0src + (kk0), 16);              \
        cp16(b1dst + so, b1src + (kk0), 16);              \
        cp_commit(); }

    LOAD1(0, 0);
    LOAD1(1, KS);
    LOAD1(2, 2*KS);

    const int NK = DM / KS;
    for (int kt = 0; kt < NK; kt++) {
        int cur = kt % NSTG;
        cp_wait2();
        __syncthreads();
        if (kt + 3 < NK) { LOAD1((kt + 3) % NSTG, (kt + 3)*KS); }
        else             { cp_commit(); }   // empty group drain

        unsigned so = cur*(unsigned)(TILE_H*2);
#pragma unroll
        for (int ks = 0; ks < KS; ks += 16) {
            unsigned A0[4], A1[4], P0[4], P1[4], Q0[4], Q1[4];
            ldsm4(A0, aLA  + so + ks*2);
            ldsm4(A1, aLA  + so + ks*2 + 16*HLD*2);
            ldsm4(P0, b0LA + so + ks*2);
            ldsm4(P1, b0LA + so + ks*2 + 16*HLD*2);
            ldsm4(Q0, b1LA + so + ks*2);
            ldsm4(Q1, b1LA + so + ks*2 + 16*HLD*2);
            mma_f16(ch[0][0], A0[0],A0[1],A0[2],A0[3], P0[0],P0[1]);
            mma_f16(ch[1][0], A1[0],A1[1],A1[2],A1[3], P0[0],P0[1]);
            mma_f16(ch[0][1], A0[0],A0[1],A0[2],A0[3], P0[2],P0[3]);
            mma_f16(ch[1][1], A1[0],A1[1],A1[2],A1[3], P0[2],P0[3]);
            mma_f16(ch[0][2], A0[0],A0[1],A0[2],A0[3], P1[0],P1[1]);
            mma_f16(ch[1][2], A1[0],A1[1],A1[2],A1[3], P1[0],P1[1]);
            mma_f16(ch[0][3], A0[0],A0[1],A0[2],A0[3], P1[2],P1[3]);
            mma_f16(ch[1][3], A1[0],A1[1],A1[2],A1[3], P1[2],P1[3]);
            mma_f16(cg[0][0], A0[0],A0[1],A0[2],A0[3], Q0[0],Q0[1]);
            mma_f16(cg[1][0], A1[0],A1[1],A1[2],A1[3], Q0[0],Q0[1]);
            mma_f16(cg[0][1], A0[0],A0[1],A0[2],A0[3], Q0[2],Q0[3]);
            mma_f16(cg[1][1], A1[0],A1[1],A1[2],A1[3], Q0[2],Q0[3]);
            mma_f16(cg[0][2], A0[0],A0[1],A0[2],A0[3], Q1[0],Q1[1]);
            mma_f16(cg[1][2], A1[0],A1[1],A1[2],A1[3], Q1[0],Q1[1]);
            mma_f16(cg[0][3], A0[0],A0[1],A0[2],A0[3], Q1[2],Q1[3]);
            mma_f16(cg[1][3], A1[0],A1[1],A1[2],A1[3], Q1[2],Q1[3]);
        }
    }

    const float* b0p = b0 + (size_t)e*DH;
    const float* b1p = b1 + (size_t)e*DH;
#pragma unroll
    for (int mi = 0; mi < 2; mi++) {
#pragma unroll
        for (int hh = 0; hh < 2; hh++) {
            int r = m0 + wm*32 + mi*16 + g + hh*8;
            if (r < cnt) {
                size_t row = (size_t)(off + r);
#pragma unroll
                for (int ni = 0; ni < 4; ni++) {
                    int c = n0 + wn*32 + ni*8 + tig*2;
                    float h0 = ch[mi][ni][hh*2+0] + b0p[c];
                    float g0 = cg[mi][ni][hh*2+0] + b1p[c];
                    float h1 = ch[mi][ni][hh*2+1] + b0p[c+1];
                    float g1 = cg[mi][ni][hh*2+1] + b1p[c+1];
                    float o0 = h0 * (g0 / (1.f + expf(-g0)));
                    float o1 = h1 * (g1 / (1.f + expf(-g1)));
                    *(__half2*)&g_acth[row*DH + c] = __floats2half2_rn(o0, o1);
                }
            }
        }
    }
}

// ================= pass B: out[token] += w * (act @ W2 + b2), all experts =================
__global__ void __launch_bounds__(512,1) k_mlp2(const float* __restrict__ b2,
                                                float* __restrict__ out) {
    int e   = blockIdx.z;
    int cnt = g_count[e];
    int m0  = blockIdx.y * 128;
    if (m0 >= cnt) return;
    int off = g_off[e];
    int n0  = blockIdx.x * 128;

    const __half* Bg = g_w2h + (size_t)e*DH*DM;   // [n][k]

    extern __shared__ __half sh[];
    __half* As = sh;                   // [4][128][40]
    __half* Bs = As + NSTG*TILE_H;

    int tid = threadIdx.x;
    int lrow = tid >> 2;
    int lch  = (tid & 3) * 8;
    int m = m0 + lrow;
    int ok = (m < cnt);
    const __half* asrc = g_acth + (size_t)(ok ? (off + m) : 0)*DH + lch;
    int asz = ok ? 16 : 0;
    unsigned adst = sptr(As + lrow*HLD + lch);
    const __half* bsrc = Bg + (size_t)(n0 + lrow)*DH + lch;
    unsigned bdst = sptr(Bs + lrow*HLD + lch);

    int lane = tid & 31, warp = tid >> 5;
    int wm = warp & 3, wn = warp >> 2;
    int g  = lane >> 2, tig = lane & 3;

    unsigned smb = sptr(As);
    unsigned aLA  = smb + ((wm*32 + (lane & 15))*HLD + (lane >> 4)*8)*2;
    unsigned bRow = wn*32 + (lane & 7) + (lane >> 4)*8;
    unsigned bCol = ((lane >> 3) & 1)*8;
    unsigned bLA  = smb + NSTG*TILE_H*2 + (bRow*HLD + bCol)*2;

    float acc[2][4][4];
#pragma unroll
    for (int mi = 0; mi < 2; mi++)
#pragma unroll
        for (int ni = 0; ni < 4; ni++)
#pragma unroll
            for (int j = 0; j < 4; j++) acc[mi][ni][j] = 0.f;

#define LOAD2(stage, kk0)  {                              \
        unsigned so = (stage)*TILE_H*2;                   \
        cp16(adst + so, asrc + (kk0), asz);               \
        cp16(bdst + so, bsrc + (kk0), 16);                \
        cp_commit(); }

    LOAD2(0, 0);
    LOAD2(1, KS);
    LOAD2(2, 2*KS);

    const int NK = DH / KS;
    for (int kt = 0; kt < NK; kt++) {
        int cur = kt % NSTG;
        cp_wait2();
        __syncthreads();
        if (kt + 3 < NK) { LOAD2((kt + 3) % NSTG, (kt + 3)*KS); }
        else             { cp_commit(); }   // empty group drain

        unsigned so = cur*(unsigned)(TILE_H*2);
#pragma unroll
        for (int ks = 0; ks < KS; ks += 16) {
            unsigned A0[4], A1[4], P0[4], P1[4];
            ldsm4(A0, aLA + so + ks*2);
            ldsm4(A1, aLA + so + ks*2 + 16*HLD*2);
            ldsm4(P0, bLA + so + ks*2);
            ldsm4(P1, bLA + so + ks*2 + 16*HLD*2);
            mma_f16(acc[0][0], A0[0],A0[1],A0[2],A0[3], P0[0],P0[1]);
            mma_f16(acc[1][0], A1[0],A1[1],A1[2],A1[3], P0[0],P0[1]);
            mma_f16(acc[0][1], A0[0],A0[1],A0[2],A0[3], P0[2],P0[3]);
            mma_f16(acc[1][1], A1[0],A1[1],A1[2],A1[3], P0[2],P0[3]);
            mma_f16(acc[0][2], A0[0],A0[1],A0[2],A0[3], P1[0],P1[1]);
            mma_f16(acc[1][2], A1[0],A1[1],A1[2],A1[3], P1[0],P1[1]);
            mma_f16(acc[0][3], A0[0],A0[1],A0[2],A0[3], P1[2],P1[3]);
            mma_f16(acc[1][3], A1[0],A1[1],A1[2],A1[3], P1[2],P1[3]);
        }
    }

    const float* b2p = b2 + (size_t)e*DM;
#pragma unroll
    for (int mi = 0; mi < 2; mi++) {
#pragma unroll
        for (int hh = 0; hh < 2; hh++) {
            int r = m0 + wm*32 + mi*16 + g + hh*8;
            if (r < cnt) {
                int tokp = g_pair_tok[off + r];
                float w = g_pair_w[off + r];
                float* orow = out + (size_t)tokp*DM;
#pragma unroll
                for (int ni = 0; ni < 4; ni++) {
                    int c = n0 + wn*32 + ni*8 + tig*2;
                    red_add_f32x2(&orow[c],
                                  w * (acc[mi][ni][hh*2+0] + b2p[c]),
                                  w * (acc[mi][ni][hh*2+1] + b2p[c+1]));
                }
            }
        }
    }
}

// ---------------- launch ----------------
#define SMEM1 (3*NSTG*TILE_H*2 + 128*4)
#define SMEM2 (2*NSTG*TILE_H*2)

extern "C" void kernel_launch(void* const* d_in, const int* in_sizes, int n_in,
                              void* d_out, int out_size) {
    const float* x  = (const float*)d_in[0];
    const float* Wg = (const float*)d_in[1];
    const float* bg = (const float*)d_in[2];
    const float* W0 = (const float*)d_in[3];
    const float* b0 = (const float*)d_in[4];
    const float* W1 = (const float*)d_in[5];
    const float* b1 = (const float*)d_in[6];
    const float* W2 = (const float*)d_in[7];
    const float* b2 = (const float*)d_in[8];
    float* out = (float*)d_out;

    static cudaStream_t s2 = 0, s3 = 0;
    static cudaEvent_t eFork = 0, eA = 0, eB = 0, eC = 0, evAsn = 0, eM1b = 0;
    if (!s2) {
        cudaFuncSetAttribute(k_mlp1, cudaFuncAttributeMaxDynamicSharedMemorySize, SMEM1);
        cudaFuncSetAttribute(k_mlp2, cudaFuncAttributeMaxDynamicSharedMemorySize, SMEM2);
        cudaStreamCreateWithFlags(&s2, cudaStreamNonBlocking);
        cudaStreamCreateWithFlags(&s3, cudaStreamNonBlocking);
        cudaEventCreateWithFlags(&eFork, cudaEventDisableTiming);
        cudaEventCreateWithFlags(&eA, cudaEventDisableTiming);
        cudaEventCreateWithFlags(&eB, cudaEventDisableTiming);
        cudaEventCreateWithFlags(&eC, cudaEventDisableTiming);
        cudaEventCreateWithFlags(&evAsn, cudaEventDisableTiming);
        cudaEventCreateWithFlags(&eM1b, cudaEventDisableTiming);
    }

    int* cntd; cudaGetSymbolAddress((void**)&cntd, g_count);

    // fork: weight conversions on s2 (halved W0/W1, then all W2)
    cudaEventRecord(eFork, 0);
    cudaStreamWaitEvent(s2, eFork, 0);
    k_tw01<<<dim3(DH/64, DM/64, 8), dim3(32,8), 0, s2>>>(W0, W1, 0);
    cudaEventRecord(eA, s2);
    k_tw01<<<dim3(DH/64, DM/64, 8), dim3(32,8), 0, s2>>>(W0, W1, 4);
    cudaEventRecord(eB, s2);
    k_tw2<<<dim3(DM/64, DH/64, NE), dim3(32,8), 0, s2>>>(W2);
    cudaEventRecord(eC, s2);

    // main stream: reset + routing chain
    cudaMemsetAsync(out, 0, (size_t)T_TOK*DM*sizeof(float), 0);
    cudaMemsetAsync(cntd, 0, NE*sizeof(int), 0);
    k_route <<<T_TOK, 256>>>(x, Wg, bg);
    k_assign<<<1, 1024>>>();
    cudaEventRecord(evAsn, 0);

    // mlp1 halves run CONCURRENTLY: half-1 on stream 0, half-2 on s3
    cudaStreamWaitEvent(0, eA, 0);
    k_mlp1<<<dim3(DH/128, 32, 4), 512, SMEM1>>>(b0, b1, 0);

    cudaStreamWaitEvent(s3, evAsn, 0);
    cudaStreamWaitEvent(s3, eB, 0);
    k_mlp1<<<dim3(DH/128, 32, 4), 512, SMEM1, s3>>>(b0, b1, 4);
    cudaEventRecord(eM1b, s3);

    // mlp2 waits: mlp1 half-1 (program order on stream 0), half-2 (eM1b), W2 (eC)
    cudaStreamWaitEvent(0, eM1b, 0);
    cudaStreamWaitEvent(0, eC, 0);
    k_mlp2<<<dim3(DM/128, 32, NE), 512, SMEM2>>>(b2, out);
}